// round 4
// baseline (speedup 1.0000x reference)
#include <cuda_runtime.h>
#include <math.h>

#define NB   16384
#define NC_S 64
#define NT_S 192
#define HD   64

// ---- scratch (no allocations allowed; static device globals) ----
__device__ float g_sigma_c[NB * NC_S];
__device__ float g_rgb_c[3 * NB * NC_S];
__device__ float g_z[NB * NT_S];
__device__ float g_sigma_f[NB * NT_S];
__device__ float g_rgb_f[3 * NB * NT_S];

// =====================================================================
// MLP kernel: one thread per sample. Weights staged in shared memory.
// h2 outputs are consumed on-the-fly into rgb/density accumulators so
// only h1[64] stays register-resident.
// =====================================================================
__global__ __launch_bounds__(256, 2) void mlp_kernel(
    const float* __restrict__ origins, const float* __restrict__ dirs,
    const float* __restrict__ nearp, const float* __restrict__ farp,
    const float* __restrict__ W1, const float* __restrict__ B1v,
    const float* __restrict__ W2, const float* __restrict__ B2v,
    const float* __restrict__ Wr, const float* __restrict__ Brv,
    const float* __restrict__ Wd, const float* __restrict__ Bdv,
    int nsamp, int fine)
{
    __shared__ __align__(16) float sW2[HD * HD];
    __shared__ float sW1[3 * HD];
    __shared__ float sWr[HD * 3];
    __shared__ float sB1[HD], sB2[HD], sWd[HD];
    __shared__ float sBr[3], sBd[1];

    int tid = threadIdx.x;
    for (int i = tid; i < HD * HD; i += 256) sW2[i] = W2[i];
    for (int i = tid; i < 3 * HD; i += 256) { sW1[i] = W1[i]; sWr[i] = Wr[i]; }
    if (tid < HD) { sB1[tid] = B1v[tid]; sB2[tid] = B2v[tid]; sWd[tid] = Wd[tid]; }
    if (tid < 3) sBr[tid] = Brv[tid];
    if (tid == 0) sBd[0] = Bdv[0];
    __syncthreads();

    int idx = blockIdx.x * 256 + tid;
    int total = NB * nsamp;
    if (idx >= total) return;

    int ray = idx / nsamp;
    int i = idx - ray * nsamp;

    float tv;
    if (fine) {
        tv = g_z[idx];
    } else {
        float nr = nearp[ray], fr = farp[ray];
        float step = (fr - nr) * (1.0f / 63.0f);
        tv = nr + step * (float)i;
    }
    float x0 = fmaf(tv, dirs[ray * 3 + 0], origins[ray * 3 + 0]);
    float x1 = fmaf(tv, dirs[ray * 3 + 1], origins[ray * 3 + 1]);
    float x2 = fmaf(tv, dirs[ray * 3 + 2], origins[ray * 3 + 2]);

    // layer 1: 3 -> 64, relu
    float h1[HD];
#pragma unroll
    for (int j = 0; j < HD; j++) {
        float v = sB1[j];
        v = fmaf(x0, sW1[j], v);
        v = fmaf(x1, sW1[HD + j], v);
        v = fmaf(x2, sW1[2 * HD + j], v);
        h1[j] = fmaxf(v, 0.f);
    }

    // layer 2 (64 -> 64, relu) fused with heads (64 -> 3 rgb, 64 -> 1 density)
    float r0 = sBr[0], r1 = sBr[1], r2 = sBr[2], den = sBd[0];
#pragma unroll 4
    for (int j = 0; j < HD; j += 4) {
        float a0 = sB2[j], a1 = sB2[j + 1], a2 = sB2[j + 2], a3 = sB2[j + 3];
#pragma unroll
        for (int k = 0; k < HD; k++) {
            float4 w = *reinterpret_cast<const float4*>(&sW2[k * HD + j]);
            float hk = h1[k];
            a0 = fmaf(hk, w.x, a0);
            a1 = fmaf(hk, w.y, a1);
            a2 = fmaf(hk, w.z, a2);
            a3 = fmaf(hk, w.w, a3);
        }
        a0 = fmaxf(a0, 0.f); a1 = fmaxf(a1, 0.f);
        a2 = fmaxf(a2, 0.f); a3 = fmaxf(a3, 0.f);
        r0 = fmaf(a0, sWr[(j + 0) * 3 + 0], r0);
        r1 = fmaf(a0, sWr[(j + 0) * 3 + 1], r1);
        r2 = fmaf(a0, sWr[(j + 0) * 3 + 2], r2);
        den = fmaf(a0, sWd[j + 0], den);
        r0 = fmaf(a1, sWr[(j + 1) * 3 + 0], r0);
        r1 = fmaf(a1, sWr[(j + 1) * 3 + 1], r1);
        r2 = fmaf(a1, sWr[(j + 1) * 3 + 2], r2);
        den = fmaf(a1, sWd[j + 1], den);
        r0 = fmaf(a2, sWr[(j + 2) * 3 + 0], r0);
        r1 = fmaf(a2, sWr[(j + 2) * 3 + 1], r1);
        r2 = fmaf(a2, sWr[(j + 2) * 3 + 2], r2);
        den = fmaf(a2, sWd[j + 2], den);
        r0 = fmaf(a3, sWr[(j + 3) * 3 + 0], r0);
        r1 = fmaf(a3, sWr[(j + 3) * 3 + 1], r1);
        r2 = fmaf(a3, sWr[(j + 3) * 3 + 2], r2);
        den = fmaf(a3, sWd[j + 3], den);
    }

    // sigmoid rgb, relu density
    r0 = 1.f / (1.f + __expf(-r0));
    r1 = 1.f / (1.f + __expf(-r1));
    r2 = 1.f / (1.f + __expf(-r2));
    den = fmaxf(den, 0.f);

    if (fine) {
        g_sigma_f[idx] = den;
        g_rgb_f[idx] = r0;
        g_rgb_f[total + idx] = r1;
        g_rgb_f[2 * total + idx] = r2;
    } else {
        g_sigma_c[idx] = den;
        g_rgb_c[idx] = r0;
        g_rgb_c[total + idx] = r1;
        g_rgb_c[2 * total + idx] = r2;
    }
}

// =====================================================================
// Coarse render + inverse-CDF sampling + sorted merge. One thread/ray.
// =====================================================================
__global__ void render_coarse_kernel(
    const float* __restrict__ origins, const float* __restrict__ dirs,
    const float* __restrict__ nearp, const float* __restrict__ farp,
    const float* __restrict__ bkgd, float* __restrict__ out)
{
    int b = blockIdx.x * blockDim.x + threadIdx.x;
    if (b >= NB) return;

    float d0 = dirs[b * 3 + 0], d1 = dirs[b * 3 + 1], d2 = dirs[b * 3 + 2];
    float nr = nearp[b], fr = farp[b];
    float step = (fr - nr) * (1.0f / 63.0f);
    float dn = sqrtf(d0 * d0 + d1 * d1 + d2 * d2);

    const int NCS = NB * NC_S;
    int base = b * NC_S;

    float wbuf[NC_S];   // needed with dynamic index later -> local mem, fine
    float cum = 0.f, c0 = 0.f, c1 = 0.f, c2 = 0.f;
    float acc = 0.f, depth = 0.f, wi = 0.f;

    for (int i = 0; i < NC_S; i++) {
        float tv = nr + step * (float)i;
        float td = (i < NC_S - 1) ? step : 1e10f;
        float dd = g_sigma_c[base + i] * (td * dn);
        float w = (1.f - __expf(-dd)) * __expf(-cum);
        cum += dd;
        wbuf[i] = w;
        c0 = fmaf(w, g_rgb_c[base + i], c0);
        c1 = fmaf(w, g_rgb_c[NCS + base + i], c1);
        c2 = fmaf(w, g_rgb_c[2 * NCS + base + i], c2);
        acc += w;
        depth = fmaf(w, tv, depth);
        wi = fmaf(w, (float)i, wi);
    }

    float* o = out + b * 16;
    o[0] = fmaf(bkgd[0], 1.f - acc, c0);
    o[1] = fmaf(bkgd[1], 1.f - acc, c1);
    o[2] = fmaf(bkgd[2], 1.f - acc, c2);
    o[3] = depth;
    o[4] = acc;

    // pts0 uses ray 0's samples (faithful quirk): linear in t ->
    // pts0 = o0*acc + d0*(near0*acc + step0 * sum(w_i * i))
    float nr0 = nearp[0], fr0 = farp[0];
    float step0 = (fr0 - nr0) * (1.0f / 63.0f);
    float s = nr0 * acc + step0 * wi;
    o[5] = fmaf(dirs[0], s, origins[0] * acc);
    o[6] = fmaf(dirs[1], s, origins[1] * acc);
    o[7] = fmaf(dirs[2], s, origins[2] * acc);

    // ---- piecewise-constant PDF: weights = wbuf[1..62] (62 entries) ----
    float ws = 0.f;
    for (int k = 1; k < NC_S - 1; k++) ws += wbuf[k];
    float pad = fmaxf(1e-5f - ws, 0.f);
    float wadd = pad * (1.0f / 62.0f);
    float invws = 1.f / (ws + pad);

    // cdf has 63 entries: [0, min(cumsum(pdf[0..60]),1), 1]; bins(m)=midpoints
    // u is increasing -> two-pointer scan; z_samples monotone -> merge with t_vals
    int p = 0;
    float cdf_p = 0.f;
    float csum = (wbuf[1] + wadd) * invws;   // cumsum through pdf[0]
    float cdf_p1 = fminf(csum, 1.f);          // cdf[1]

    int ti = 0, oi = 0;
    float* zrow = g_z + b * NT_S;
    const float ustep = (1.0f - 1.1920929e-07f) * (1.0f / 127.0f);

    for (int j = 0; j < 128; j++) {
        float u = (float)j * ustep;
        while (cdf_p1 <= u) {
            p++;
            cdf_p = cdf_p1;
            if (p >= 61) cdf_p1 = 1.f;                       // cdf[62] = 1
            else { csum += (wbuf[p + 1] + wadd) * invws; cdf_p1 = fminf(csum, 1.f); }
        }
        float tt = (u - cdf_p) / (cdf_p1 - cdf_p);            // denom > 0 guaranteed
        tt = fminf(fmaxf(tt, 0.f), 1.f);
        float bg0 = nr + step * ((float)p + 0.5f);
        float bg1 = nr + step * ((float)p + 1.5f);
        float zs = bg0 + tt * (bg1 - bg0);
        // merge t_vals stream
        while (ti < NC_S && nr + step * (float)ti <= zs) {
            zrow[oi++] = nr + step * (float)ti;
            ti++;
        }
        zrow[oi++] = zs;
    }
    while (ti < NC_S) {
        zrow[oi++] = nr + step * (float)ti;
        ti++;
    }
}

// =====================================================================
// Fine render. One thread/ray. pts1 uses ray 0's z row (broadcast read).
// =====================================================================
__global__ void render_fine_kernel(
    const float* __restrict__ origins, const float* __restrict__ dirs,
    const float* __restrict__ bkgd, float* __restrict__ out)
{
    int b = blockIdx.x * blockDim.x + threadIdx.x;
    if (b >= NB) return;

    float d0 = dirs[b * 3 + 0], d1 = dirs[b * 3 + 1], d2 = dirs[b * 3 + 2];
    float dn = sqrtf(d0 * d0 + d1 * d1 + d2 * d2);

    const int NTS = NB * NT_S;
    int base = b * NT_S;

    float cum = 0.f, c0 = 0.f, c1 = 0.f, c2 = 0.f;
    float acc = 0.f, depth = 0.f, pz = 0.f;

    float zc = g_z[base];
    for (int j = 0; j < NT_S; j++) {
        float zn = (j < NT_S - 1) ? g_z[base + j + 1] : 0.f;
        float td = (j < NT_S - 1) ? (zn - zc) : 1e10f;
        float dd = g_sigma_f[base + j] * (td * dn);
        float w = (1.f - __expf(-dd)) * __expf(-cum);
        cum += dd;
        c0 = fmaf(w, g_rgb_f[base + j], c0);
        c1 = fmaf(w, g_rgb_f[NTS + base + j], c1);
        c2 = fmaf(w, g_rgb_f[2 * NTS + base + j], c2);
        acc += w;
        depth = fmaf(w, zc, depth);
        pz = fmaf(w, g_z[j], pz);    // ray 0's z_vals (broadcast, L1/L2 hit)
        zc = zn;
    }

    float* o = out + b * 16;
    o[8]  = fmaf(bkgd[0], 1.f - acc, c0);
    o[9]  = fmaf(bkgd[1], 1.f - acc, c1);
    o[10] = fmaf(bkgd[2], 1.f - acc, c2);
    o[11] = depth;
    o[12] = acc;
    // pts1 = o0*acc + d0 * sum(w_j * z0_j)
    o[13] = fmaf(dirs[0], pz, origins[0] * acc);
    o[14] = fmaf(dirs[1], pz, origins[1] * acc);
    o[15] = fmaf(dirs[2], pz, origins[2] * acc);
}

// =====================================================================
extern "C" void kernel_launch(void* const* d_in, const int* in_sizes, int n_in,
                              void* d_out, int out_size)
{
    (void)in_sizes; (void)n_in; (void)out_size;
    const float* origins = (const float*)d_in[0];
    const float* dirs    = (const float*)d_in[1];
    const float* nearp   = (const float*)d_in[2];
    const float* farp    = (const float*)d_in[3];
    const float* bkgd    = (const float*)d_in[4];
    const float* w1c = (const float*)d_in[5];  const float* b1c = (const float*)d_in[6];
    const float* w2c = (const float*)d_in[7];  const float* b2c = (const float*)d_in[8];
    const float* wrc = (const float*)d_in[9];  const float* brc = (const float*)d_in[10];
    const float* wdc = (const float*)d_in[11]; const float* bdc = (const float*)d_in[12];
    const float* w1f = (const float*)d_in[13]; const float* b1f = (const float*)d_in[14];
    const float* w2f = (const float*)d_in[15]; const float* b2f = (const float*)d_in[16];
    const float* wrf = (const float*)d_in[17]; const float* brf = (const float*)d_in[18];
    const float* wdf = (const float*)d_in[19]; const float* bdf = (const float*)d_in[20];
    float* out = (float*)d_out;

    mlp_kernel<<<NB * NC_S / 256, 256>>>(origins, dirs, nearp, farp,
                                         w1c, b1c, w2c, b2c, wrc, brc, wdc, bdc,
                                         NC_S, 0);
    render_coarse_kernel<<<(NB + 255) / 256, 256>>>(origins, dirs, nearp, farp, bkgd, out);
    mlp_kernel<<<NB * NT_S / 256, 256>>>(origins, dirs, nearp, farp,
                                         w1f, b1f, w2f, b2f, wrf, brf, wdf, bdf,
                                         NT_S, 1);
    render_fine_kernel<<<(NB + 255) / 256, 256>>>(origins, dirs, bkgd, out);
}

// round 12
// speedup vs baseline: 2.2220x; 2.2220x over previous
#include <cuda_runtime.h>
#include <cuda_bf16.h>
#include <cstdint>
#include <math.h>

#define NB   16384
#define NCS  64
#define NTS  192
#define HD   64

// ---- scratch (no allocations allowed; static device globals) ----
__device__ float g_z[NB * NTS];
__device__ float g_sigma_c[NB * NCS];
__device__ float g_rgb_c[3 * NB * NCS];
__device__ float g_sigma_f[NB * NTS];
__device__ float g_rgb_f[3 * NB * NTS];

// =====================================================================
// base-target (sm_80+) tensor-core mma.sync bf16; fragments loaded with
// plain 32-bit LDS at the documented per-lane (row,col) coordinates —
// no ldmatrix, no layout ambiguity.
// =====================================================================
#define MMA16816(d, a, b0, b1) \
    asm volatile("mma.sync.aligned.m16n8k16.row.col.f32.bf16.bf16.f32 " \
        "{%0,%1,%2,%3}, {%4,%5,%6,%7}, {%8,%9}, {%0,%1,%2,%3};" \
        : "+f"((d)[0]), "+f"((d)[1]), "+f"((d)[2]), "+f"((d)[3]) \
        : "r"((a)[0]), "r"((a)[1]), "r"((a)[2]), "r"((a)[3]), "r"(b0), "r"(b1))

// A tile (per warp): 32 rows x 40 bf16 (32 data + 8 pad) -> 20 words/row,
// lane word pattern 20g+q mod 32 -> conflict-free.
#define A_STRIDE 40
// B tile: 64 rows (n) x 72 bf16 -> 36 words/row, 36g+q ≡ 4g+q -> conflict-free.
#define B_STRIDE 72

__device__ __forceinline__ uint32_t ld_u32(const __nv_bfloat16* p) {
    return *reinterpret_cast<const uint32_t*>(p);
}

// =====================================================================
// MLP kernel: warp-per-32-sample tiles, persistent grid.
//   layer1 scalar fp32 -> h1 bf16 hi/lo in SMEM -> 3-pass mma.sync
//   (Ahi*Bhi + Alo*Bhi + Ahi*Blo ~= fp32) -> epilogue heads thread-local
//   + shfl butterfly reduce.
// =====================================================================
template <int NS>
__global__ __launch_bounds__(128, 3) void mlp_mma_kernel(
    const float* __restrict__ origins, const float* __restrict__ dirs,
    const float* __restrict__ nearp, const float* __restrict__ farp,
    const float* __restrict__ W1, const float* __restrict__ B1v,
    const float* __restrict__ W2, const float* __restrict__ B2v,
    const float* __restrict__ Wr, const float* __restrict__ Brv,
    const float* __restrict__ Wd, const float* __restrict__ Bdv)
{
    __shared__ __align__(16) __nv_bfloat16 sAhi[4 * 32 * A_STRIDE];   // 10.0 KB
    __shared__ __align__(16) __nv_bfloat16 sAlo[4 * 32 * A_STRIDE];   // 10.0 KB
    __shared__ __align__(16) __nv_bfloat16 sBhi[HD * B_STRIDE];       //  9.0 KB
    __shared__ __align__(16) __nv_bfloat16 sBlo[HD * B_STRIDE];       //  9.0 KB
    __shared__ float4 sL1[HD];      // (w1x, w1y, w1z, b1) per hidden unit
    __shared__ float4 sHead[HD];    // (wr0, wr1, wr2, wd) per hidden unit
    __shared__ float  sB2[HD];
    __shared__ float  sBias[4];

    const int tid = threadIdx.x;
    const int wid = tid >> 5;
    const int lane = tid & 31;
    const int g = lane >> 2;                  // groupID (0..7)
    const int q = lane & 3;                   // thread-in-group (0..3)

    // ---- stage weights (once per CTA) ----
    for (int idx = tid; idx < HD * HD; idx += 128) {
        int n = idx >> 6, k = idx & 63;       // B[n][k] = W2[k][n]
        float w = W2[k * HD + n];
        __nv_bfloat16 hi = __float2bfloat16(w);
        float lo = w - __bfloat162float(hi);
        sBhi[n * B_STRIDE + k] = hi;
        sBlo[n * B_STRIDE + k] = __float2bfloat16(lo);
    }
    if (tid < HD) {
        sL1[tid] = make_float4(W1[tid], W1[HD + tid], W1[2 * HD + tid], B1v[tid]);
        sHead[tid] = make_float4(Wr[tid * 3 + 0], Wr[tid * 3 + 1], Wr[tid * 3 + 2], Wd[tid]);
        sB2[tid] = B2v[tid];
    }
    if (tid < 3) sBias[tid] = Brv[tid];
    if (tid == 0) sBias[3] = Bdv[0];
    __syncthreads();

    __nv_bfloat16* aHi = sAhi + wid * 32 * A_STRIDE;   // this warp's A tile
    __nv_bfloat16* aLo = sAlo + wid * 32 * A_STRIDE;
    __nv_bfloat16* aHiRow = aHi + lane * A_STRIDE;     // this thread's sample row
    __nv_bfloat16* aLoRow = aLo + lane * A_STRIDE;

    const int nTiles = NB * NS / 32;
    const int wstride = gridDim.x * 4;

    for (int t = blockIdx.x * 4 + wid; t < nTiles; t += wstride) {
        // ---- per-sample ray position (thread = sample t*32 + lane) ----
        const int s = t * 32 + lane;
        const int ray = s / NS;
        const int i = s - ray * NS;
        float tv;
        if (NS == NTS) {
            tv = g_z[s];
        } else {
            float nr = nearp[ray];
            tv = fmaf((farp[ray] - nr) * (1.0f / 63.0f), (float)i, nr);
        }
        const float x0 = fmaf(tv, dirs[ray * 3 + 0], origins[ray * 3 + 0]);
        const float x1 = fmaf(tv, dirs[ray * 3 + 1], origins[ray * 3 + 1]);
        const float x2 = fmaf(tv, dirs[ray * 3 + 2], origins[ray * 3 + 2]);

        float acc[2][8][4];
#pragma unroll
        for (int m = 0; m < 2; m++)
#pragma unroll
            for (int n = 0; n < 8; n++)
#pragma unroll
                for (int o = 0; o < 4; o++) acc[m][n][o] = 0.f;

        // ---- two k-halves: layer1(32 units) -> SMEM -> mma over 2 k-tiles ----
#pragma unroll
        for (int kh = 0; kh < 2; kh++) {
            __syncwarp();
            uint32_t phi[16], plo[16];
#pragma unroll
            for (int c = 0; c < 16; c++) {
                float4 wa = sL1[kh * 32 + 2 * c];
                float4 wb = sL1[kh * 32 + 2 * c + 1];
                float h0 = fmaf(x2, wa.z, fmaf(x1, wa.y, fmaf(x0, wa.x, wa.w)));
                float h1 = fmaf(x2, wb.z, fmaf(x1, wb.y, fmaf(x0, wb.x, wb.w)));
                h0 = fmaxf(h0, 0.f); h1 = fmaxf(h1, 0.f);
                uint32_t u0 = __float_as_uint(h0), u1 = __float_as_uint(h1);
                phi[c] = __byte_perm(u0, u1, 0x7632);   // {trunc_bf16(h0), trunc_bf16(h1)}
                float l0 = h0 - __uint_as_float(u0 & 0xFFFF0000u);
                float l1 = h1 - __uint_as_float(u1 & 0xFFFF0000u);
                asm("cvt.rn.bf16x2.f32 %0, %1, %2;" : "=r"(plo[c]) : "f"(l1), "f"(l0));
            }
#pragma unroll
            for (int c = 0; c < 4; c++) {
                *reinterpret_cast<uint4*>(aHiRow + c * 8) = reinterpret_cast<uint4*>(phi)[c];
                *reinterpret_cast<uint4*>(aLoRow + c * 8) = reinterpret_cast<uint4*>(plo)[c];
            }
            __syncwarp();

#pragma unroll
            for (int kt2 = 0; kt2 < 2; kt2++) {
                // --- A fragments: direct LDS per PTX m16n8k16 coordinates ---
                // a0:(row g, k 2q) a1:(row g+8, k 2q) a2:(g, 2q+8) a3:(g+8, 2q+8)
                uint32_t ah[2][4], al[2][4];
#pragma unroll
                for (int mt = 0; mt < 2; mt++) {
                    const __nv_bfloat16* ap = aHi + (mt * 16 + g) * A_STRIDE + kt2 * 16 + 2 * q;
                    ah[mt][0] = ld_u32(ap);
                    ah[mt][1] = ld_u32(ap + 8 * A_STRIDE);
                    ah[mt][2] = ld_u32(ap + 8);
                    ah[mt][3] = ld_u32(ap + 8 * A_STRIDE + 8);
                    const __nv_bfloat16* lp = aLo + (mt * 16 + g) * A_STRIDE + kt2 * 16 + 2 * q;
                    al[mt][0] = ld_u32(lp);
                    al[mt][1] = ld_u32(lp + 8 * A_STRIDE);
                    al[mt][2] = ld_u32(lp + 8);
                    al[mt][3] = ld_u32(lp + 8 * A_STRIDE + 8);
                }
                const int kg = kh * 32 + kt2 * 16;      // global k base for B
#pragma unroll
                for (int nt = 0; nt < 8; nt++) {
                    // b0:(k 2q, n g)  b1:(k 2q+8, n g)
                    const __nv_bfloat16* bp = sBhi + (nt * 8 + g) * B_STRIDE + kg + 2 * q;
                    uint32_t bh0 = ld_u32(bp), bh1 = ld_u32(bp + 8);
                    const __nv_bfloat16* cp = sBlo + (nt * 8 + g) * B_STRIDE + kg + 2 * q;
                    uint32_t bl0 = ld_u32(cp), bl1 = ld_u32(cp + 8);
#pragma unroll
                    for (int mt = 0; mt < 2; mt++) {
                        MMA16816(acc[mt][nt], ah[mt], bh0, bh1);
                        MMA16816(acc[mt][nt], al[mt], bh0, bh1);
                        MMA16816(acc[mt][nt], ah[mt], bl0, bl1);
                    }
                }
            }
        }

        // ---- epilogue: h2 = relu(acc + b2[col]); heads thread-local ----
        // D frag: acc[mt][nt] = {(row g, c0), (g, c0+1), (g+8, c0), (g+8, c0+1)}
        // with c0 = nt*8 + 2q.
        float p[2][2][4];
#pragma unroll
        for (int m = 0; m < 2; m++)
#pragma unroll
            for (int h = 0; h < 2; h++)
#pragma unroll
                for (int o = 0; o < 4; o++) p[m][h][o] = 0.f;

#pragma unroll
        for (int nt = 0; nt < 8; nt++) {
            int c0 = nt * 8 + 2 * q;
            float b2a = sB2[c0], b2b = sB2[c0 + 1];
            float4 ha = sHead[c0], hb = sHead[c0 + 1];
#pragma unroll
            for (int mt = 0; mt < 2; mt++) {
                float h0 = fmaxf(acc[mt][nt][0] + b2a, 0.f);
                float h1 = fmaxf(acc[mt][nt][1] + b2b, 0.f);
                float h2 = fmaxf(acc[mt][nt][2] + b2a, 0.f);
                float h3 = fmaxf(acc[mt][nt][3] + b2b, 0.f);
                p[mt][0][0] = fmaf(h0, ha.x, fmaf(h1, hb.x, p[mt][0][0]));
                p[mt][0][1] = fmaf(h0, ha.y, fmaf(h1, hb.y, p[mt][0][1]));
                p[mt][0][2] = fmaf(h0, ha.z, fmaf(h1, hb.z, p[mt][0][2]));
                p[mt][0][3] = fmaf(h0, ha.w, fmaf(h1, hb.w, p[mt][0][3]));
                p[mt][1][0] = fmaf(h2, ha.x, fmaf(h3, hb.x, p[mt][1][0]));
                p[mt][1][1] = fmaf(h2, ha.y, fmaf(h3, hb.y, p[mt][1][1]));
                p[mt][1][2] = fmaf(h2, ha.z, fmaf(h3, hb.z, p[mt][1][2]));
                p[mt][1][3] = fmaf(h2, ha.w, fmaf(h3, hb.w, p[mt][1][3]));
            }
        }
        // reduce over the 4 lanes sharing each row-group (lanes 4g..4g+3)
#pragma unroll
        for (int m = 0; m < 2; m++)
#pragma unroll
            for (int h = 0; h < 2; h++)
#pragma unroll
                for (int o = 0; o < 4; o++) {
                    float v = p[m][h][o];
                    v += __shfl_xor_sync(0xffffffffu, v, 1);
                    v += __shfl_xor_sync(0xffffffffu, v, 2);
                    p[m][h][o] = v;
                }

        // lane q in each group writes row (q>>1)*16 + (q&1)*8 + g
        const int mtw = q >> 1, hfw = q & 1;
        float r0 = p[mtw][hfw][0] + sBias[0];
        float r1 = p[mtw][hfw][1] + sBias[1];
        float r2 = p[mtw][hfw][2] + sBias[2];
        float den = fmaxf(p[mtw][hfw][3] + sBias[3], 0.f);
        r0 = 1.f / (1.f + __expf(-r0));
        r1 = 1.f / (1.f + __expf(-r1));
        r2 = 1.f / (1.f + __expf(-r2));

        const int sw = t * 32 + mtw * 16 + hfw * 8 + g;
        if (NS == NTS) {
            const int P = NB * NTS;
            g_sigma_f[sw] = den;
            g_rgb_f[sw] = r0; g_rgb_f[P + sw] = r1; g_rgb_f[2 * P + sw] = r2;
        } else {
            const int P = NB * NCS;
            g_sigma_c[sw] = den;
            g_rgb_c[sw] = r0; g_rgb_c[P + sw] = r1; g_rgb_c[2 * P + sw] = r2;
        }
    }
}

// =====================================================================
// Coarse render + inverse-CDF sampling + sorted merge. One thread/ray.
// (proven round-4 version)
// =====================================================================
__global__ void render_coarse_kernel(
    const float* __restrict__ origins, const float* __restrict__ dirs,
    const float* __restrict__ nearp, const float* __restrict__ farp,
    const float* __restrict__ bkgd, float* __restrict__ out)
{
    int b = blockIdx.x * blockDim.x + threadIdx.x;
    if (b >= NB) return;

    float d0 = dirs[b * 3 + 0], d1 = dirs[b * 3 + 1], d2 = dirs[b * 3 + 2];
    float nr = nearp[b], fr = farp[b];
    float step = (fr - nr) * (1.0f / 63.0f);
    float dn = sqrtf(d0 * d0 + d1 * d1 + d2 * d2);

    const int P = NB * NCS;
    int base = b * NCS;

    float wbuf[NCS];
    float cum = 0.f, c0 = 0.f, c1 = 0.f, c2 = 0.f;
    float acc = 0.f, depth = 0.f, wi = 0.f;

    for (int i = 0; i < NCS; i++) {
        float tv = nr + step * (float)i;
        float td = (i < NCS - 1) ? step : 1e10f;
        float dd = g_sigma_c[base + i] * (td * dn);
        float w = (1.f - __expf(-dd)) * __expf(-cum);
        cum += dd;
        wbuf[i] = w;
        c0 = fmaf(w, g_rgb_c[base + i], c0);
        c1 = fmaf(w, g_rgb_c[P + base + i], c1);
        c2 = fmaf(w, g_rgb_c[2 * P + base + i], c2);
        acc += w;
        depth = fmaf(w, tv, depth);
        wi = fmaf(w, (float)i, wi);
    }

    float* o = out + b * 16;
    o[0] = fmaf(bkgd[0], 1.f - acc, c0);
    o[1] = fmaf(bkgd[1], 1.f - acc, c1);
    o[2] = fmaf(bkgd[2], 1.f - acc, c2);
    o[3] = depth;
    o[4] = acc;

    // pts0 uses ray 0's samples (faithful quirk), linear in t
    float nr0 = nearp[0], fr0 = farp[0];
    float step0 = (fr0 - nr0) * (1.0f / 63.0f);
    float s = nr0 * acc + step0 * wi;
    o[5] = fmaf(dirs[0], s, origins[0] * acc);
    o[6] = fmaf(dirs[1], s, origins[1] * acc);
    o[7] = fmaf(dirs[2], s, origins[2] * acc);

    // ---- piecewise-constant PDF: weights = wbuf[1..62] ----
    float ws = 0.f;
    for (int k = 1; k < NCS - 1; k++) ws += wbuf[k];
    float pad = fmaxf(1e-5f - ws, 0.f);
    float wadd = pad * (1.0f / 62.0f);
    float invws = 1.f / (ws + pad);

    int p = 0;
    float cdf_p = 0.f;
    float csum = (wbuf[1] + wadd) * invws;
    float cdf_p1 = fminf(csum, 1.f);

    int ti = 0, oi = 0;
    float* zrow = g_z + b * NTS;
    const float ustep = (1.0f - 1.1920929e-07f) * (1.0f / 127.0f);

    for (int j = 0; j < 128; j++) {
        float u = (float)j * ustep;
        while (cdf_p1 <= u) {
            p++;
            cdf_p = cdf_p1;
            if (p >= 61) cdf_p1 = 1.f;
            else { csum += (wbuf[p + 1] + wadd) * invws; cdf_p1 = fminf(csum, 1.f); }
        }
        float tt = (u - cdf_p) / (cdf_p1 - cdf_p);
        tt = fminf(fmaxf(tt, 0.f), 1.f);
        float bg0 = nr + step * ((float)p + 0.5f);
        float bg1 = nr + step * ((float)p + 1.5f);
        float zs = bg0 + tt * (bg1 - bg0);
        while (ti < NCS && nr + step * (float)ti <= zs) {
            zrow[oi++] = nr + step * (float)ti;
            ti++;
        }
        zrow[oi++] = zs;
    }
    while (ti < NCS) {
        zrow[oi++] = nr + step * (float)ti;
        ti++;
    }
}

// =====================================================================
// Fine render. One thread/ray. (proven round-4 version)
// =====================================================================
__global__ void render_fine_kernel(
    const float* __restrict__ origins, const float* __restrict__ dirs,
    const float* __restrict__ bkgd, float* __restrict__ out)
{
    int b = blockIdx.x * blockDim.x + threadIdx.x;
    if (b >= NB) return;

    float d0 = dirs[b * 3 + 0], d1 = dirs[b * 3 + 1], d2 = dirs[b * 3 + 2];
    float dn = sqrtf(d0 * d0 + d1 * d1 + d2 * d2);

    const int P = NB * NTS;
    int base = b * NTS;

    float cum = 0.f, c0 = 0.f, c1 = 0.f, c2 = 0.f;
    float acc = 0.f, depth = 0.f, pz = 0.f;

    float zc = g_z[base];
    for (int j = 0; j < NTS; j++) {
        float zn = (j < NTS - 1) ? g_z[base + j + 1] : 0.f;
        float td = (j < NTS - 1) ? (zn - zc) : 1e10f;
        float dd = g_sigma_f[base + j] * (td * dn);
        float w = (1.f - __expf(-dd)) * __expf(-cum);
        cum += dd;
        c0 = fmaf(w, g_rgb_f[base + j], c0);
        c1 = fmaf(w, g_rgb_f[P + base + j], c1);
        c2 = fmaf(w, g_rgb_f[2 * P + base + j], c2);
        acc += w;
        depth = fmaf(w, zc, depth);
        pz = fmaf(w, g_z[j], pz);    // ray 0's z_vals (broadcast, cached)
        zc = zn;
    }

    float* o = out + b * 16;
    o[8]  = fmaf(bkgd[0], 1.f - acc, c0);
    o[9]  = fmaf(bkgd[1], 1.f - acc, c1);
    o[10] = fmaf(bkgd[2], 1.f - acc, c2);
    o[11] = depth;
    o[12] = acc;
    o[13] = fmaf(dirs[0], pz, origins[0] * acc);
    o[14] = fmaf(dirs[1], pz, origins[1] * acc);
    o[15] = fmaf(dirs[2], pz, origins[2] * acc);
}

// =====================================================================
extern "C" void kernel_launch(void* const* d_in, const int* in_sizes, int n_in,
                              void* d_out, int out_size)
{
    (void)in_sizes; (void)n_in; (void)out_size;
    const float* origins = (const float*)d_in[0];
    const float* dirs    = (const float*)d_in[1];
    const float* nearp   = (const float*)d_in[2];
    const float* farp    = (const float*)d_in[3];
    const float* bkgd    = (const float*)d_in[4];
    const float* w1c = (const float*)d_in[5];  const float* b1c = (const float*)d_in[6];
    const float* w2c = (const float*)d_in[7];  const float* b2c = (const float*)d_in[8];
    const float* wrc = (const float*)d_in[9];  const float* brc = (const float*)d_in[10];
    const float* wdc = (const float*)d_in[11]; const float* bdc = (const float*)d_in[12];
    const float* w1f = (const float*)d_in[13]; const float* b1f = (const float*)d_in[14];
    const float* w2f = (const float*)d_in[15]; const float* b2f = (const float*)d_in[16];
    const float* wrf = (const float*)d_in[17]; const float* brf = (const float*)d_in[18];
    const float* wdf = (const float*)d_in[19]; const float* bdf = (const float*)d_in[20];
    float* out = (float*)d_out;

    const int GRID = 148 * 3;

    mlp_mma_kernel<NCS><<<GRID, 128>>>(origins, dirs, nearp, farp,
                                       w1c, b1c, w2c, b2c, wrc, brc, wdc, bdc);
    render_coarse_kernel<<<(NB + 255) / 256, 256>>>(origins, dirs, nearp, farp, bkgd, out);
    mlp_mma_kernel<NTS><<<GRID, 128>>>(origins, dirs, nearp, farp,
                                       w1f, b1f, w2f, b2f, wrf, brf, wdf, bdf);
    render_fine_kernel<<<(NB + 255) / 256, 256>>>(origins, dirs, bkgd, out);
}